// round 2
// baseline (speedup 1.0000x reference)
#include <cuda_runtime.h>
#include <math.h>

#define NMAX 100000
#define FDIM 64
#define PITCH 68   // 68 floats = 272 bytes, 16B-aligned rows (65 was misaligned for float4)

// Scratch (static device globals — no runtime allocation allowed)
__device__ float g_pe[(size_t)NMAX * FDIM];
__device__ float g_mj[(size_t)NMAX * FDIM];
__device__ float g_v [(size_t)NMAX * FDIM];

__device__ __forceinline__ float sp_f(float x) {
    // softplus(x) = max(x,0) + log1p(exp(-|x|))  (numerically stable)
    return fmaxf(x, 0.0f) + log1pf(__expf(-fabsf(x)));
}

// ---------------------------------------------------------------------------
// K1: per-atom precompute.
//   pe = sp(emb);  v0 = sp(pe@Wi^T + bi);  mj = sp(pe@Wj^T + bj)
// One block = 64-atom tile, 256 threads, thread computes 4x4 output tile.
// ---------------------------------------------------------------------------
__global__ void __launch_bounds__(256) k1_atom(
    const float* __restrict__ emb,
    const float* __restrict__ W_i, const float* __restrict__ b_i,
    const float* __restrict__ W_j, const float* __restrict__ b_j,
    int N)
{
    __shared__ float xs[64 * PITCH];
    __shared__ float ws[64 * 64];
    __shared__ float bs[64];
    int t  = threadIdx.x;
    int tx = t & 15, ty = t >> 4;
    int base = blockIdx.x * 64;

    #pragma unroll
    for (int i = 0; i < 4; i++) {
        int r = ty * 4 + i;
        int row = base + r;
        float4 v = make_float4(0.f, 0.f, 0.f, 0.f);
        if (row < N) v = *(const float4*)(emb + (size_t)row * 64 + tx * 4);
        v.x = sp_f(v.x); v.y = sp_f(v.y); v.z = sp_f(v.z); v.w = sp_f(v.w);
        *(float4*)(xs + r * PITCH + tx * 4) = v;
        if (row < N) *(float4*)(g_pe + (size_t)row * 64 + tx * 4) = v;
    }

    for (int pass = 0; pass < 2; pass++) {
        const float* W = pass ? W_j : W_i;
        const float* B = pass ? b_j : b_i;
        float* dst = pass ? g_mj : g_v;
        __syncthreads();
        // ws[k*64+c] = W[c*64+k]  (transposed for conflict-free b-fragment reads)
        for (int idx = t; idx < 4096; idx += 256)
            ws[(idx & 63) * 64 + (idx >> 6)] = W[idx];
        if (t < 64) bs[t] = B[t];
        __syncthreads();

        float acc[4][4] = {};
        #pragma unroll 8
        for (int k = 0; k < 64; k++) {
            float4 b4 = *(const float4*)(ws + k * 64 + tx * 4);
            #pragma unroll
            for (int i = 0; i < 4; i++) {
                float a = xs[(ty * 4 + i) * PITCH + k];
                acc[i][0] = fmaf(a, b4.x, acc[i][0]);
                acc[i][1] = fmaf(a, b4.y, acc[i][1]);
                acc[i][2] = fmaf(a, b4.z, acc[i][2]);
                acc[i][3] = fmaf(a, b4.w, acc[i][3]);
            }
        }
        #pragma unroll
        for (int i = 0; i < 4; i++) {
            int row = base + ty * 4 + i;
            if (row < N) {
                float4 o;
                o.x = sp_f(acc[i][0] + bs[tx * 4 + 0]);
                o.y = sp_f(acc[i][1] + bs[tx * 4 + 1]);
                o.z = sp_f(acc[i][2] + bs[tx * 4 + 2]);
                o.w = sp_f(acc[i][3] + bs[tx * 4 + 3]);
                *(float4*)(dst + (size_t)row * 64 + tx * 4) = o;
            }
        }
    }
}

// ---------------------------------------------------------------------------
// K2: pair scatter.  g = f_ij @ Wg^T;  v[idx_i] += mj[idx_j] * g (atomics)
// One warp = one pair per iteration; W_g held in registers (2 cols per lane);
// f_ij staged in shared per 8-pair block chunk.
// ---------------------------------------------------------------------------
__global__ void __launch_bounds__(256) k2_pair(
    const float* __restrict__ f_ij,
    const int*   __restrict__ pidx,
    const float* __restrict__ W_g,
    int P)
{
    __shared__ float fs[8][16];
    __shared__ int   si[8], sj[8];
    int t = threadIdx.x;
    int lane = t & 31, w = t >> 5;
    int c0 = lane * 2;
    float wg0[16], wg1[16];
    #pragma unroll
    for (int k = 0; k < 16; k++) {
        wg0[k] = W_g[c0 * 16 + k];
        wg1[k] = W_g[(c0 + 1) * 16 + k];
    }

    for (int base = blockIdx.x * 8; base < P; base += gridDim.x * 8) {
        __syncthreads();
        if (t < 128) {
            int p = base + (t >> 4);
            if (p < P) fs[t >> 4][t & 15] = f_ij[(size_t)p * 16 + (t & 15)];
        }
        if (t < 8) {
            int p = base + t;
            if (p < P) { si[t] = pidx[p]; sj[t] = pidx[P + p]; }
        }
        __syncthreads();
        int p = base + w;
        if (p < P) {
            int ai = si[w], aj = sj[w];
            float2 m = *(const float2*)(g_mj + (size_t)aj * 64 + c0);
            float a0 = 0.f, a1 = 0.f;
            #pragma unroll
            for (int k = 0; k < 16; k++) {
                float fk = fs[w][k];
                a0 = fmaf(fk, wg0[k], a0);
                a1 = fmaf(fk, wg1[k], a1);
            }
            float* d = g_v + (size_t)ai * 64 + c0;
            atomicAdd(d,     m.x * a0);
            atomicAdd(d + 1, m.y * a1);
        }
    }
}

// ---------------------------------------------------------------------------
// K3: fused residual chain + output. All 11 weight matrices resident in
// shared (~214KB), one block per SM, grid-stride over 64-atom tiles.
// ---------------------------------------------------------------------------
__device__ __forceinline__ void mm64(const float* __restrict__ x,
                                     const float* __restrict__ w,
                                     int tx, int ty, float acc[4][4])
{
    #pragma unroll 8
    for (int k = 0; k < 64; k++) {
        float4 b4 = *(const float4*)(w + k * 64 + tx * 4);
        #pragma unroll
        for (int i = 0; i < 4; i++) {
            float a = x[(ty * 4 + i) * PITCH + k];
            acc[i][0] = fmaf(a, b4.x, acc[i][0]);
            acc[i][1] = fmaf(a, b4.y, acc[i][1]);
            acc[i][2] = fmaf(a, b4.z, acc[i][2]);
            acc[i][3] = fmaf(a, b4.w, acc[i][3]);
        }
    }
}

__device__ __forceinline__ void residual64(float* V, float* S,
                                           const float* w1, const float* b1,
                                           const float* w2, const float* b2,
                                           int tx, int ty)
{
    __syncthreads();
    #pragma unroll
    for (int i = 0; i < 4; i++) {
        float4 v = *(float4*)(V + (ty * 4 + i) * PITCH + tx * 4);
        v.x = sp_f(v.x); v.y = sp_f(v.y); v.z = sp_f(v.z); v.w = sp_f(v.w);
        *(float4*)(S + (ty * 4 + i) * PITCH + tx * 4) = v;
    }
    __syncthreads();
    float acc[4][4] = {};
    mm64(S, w1, tx, ty, acc);
    __syncthreads();
    #pragma unroll
    for (int i = 0; i < 4; i++) {
        float4 h;
        h.x = sp_f(acc[i][0] + b1[tx * 4 + 0]);
        h.y = sp_f(acc[i][1] + b1[tx * 4 + 1]);
        h.z = sp_f(acc[i][2] + b1[tx * 4 + 2]);
        h.w = sp_f(acc[i][3] + b1[tx * 4 + 3]);
        *(float4*)(S + (ty * 4 + i) * PITCH + tx * 4) = h;
    }
    __syncthreads();
    float acc2[4][4] = {};
    mm64(S, w2, tx, ty, acc2);
    #pragma unroll
    for (int i = 0; i < 4; i++) {
        float4 v = *(float4*)(V + (ty * 4 + i) * PITCH + tx * 4);
        v.x += acc2[i][0] + b2[tx * 4 + 0];
        v.y += acc2[i][1] + b2[tx * 4 + 1];
        v.z += acc2[i][2] + b2[tx * 4 + 2];
        v.w += acc2[i][3] + b2[tx * 4 + 3];
        *(float4*)(V + (ty * 4 + i) * PITCH + tx * 4) = v;
    }
}

__global__ void __launch_bounds__(256) k3_out(
    const float* __restrict__ rin_W1, const float* __restrict__ rin_b1,
    const float* __restrict__ rin_W2, const float* __restrict__ rin_b2,
    const float* __restrict__ rout_W1, const float* __restrict__ rout_b1,
    const float* __restrict__ rout_W2, const float* __restrict__ rout_b2,
    const float* __restrict__ W_v, const float* __restrict__ b_v,
    const float* __restrict__ gate,
    const float* __restrict__ W_out, const float* __restrict__ b_out,
    float* __restrict__ pred, float* __restrict__ upd, int N)
{
    extern __shared__ float sm[];
    float* WS = sm;                    // 11 * 4096
    float* V  = WS + 11 * 4096;        // 64 * PITCH
    float* S  = V + 64 * PITCH;        // 64 * PITCH
    float* SB = S + 64 * PITCH;        // ~900 floats of small params
    int t = threadIdx.x, tx = t & 15, ty = t >> 4;

    // Load all weights once per block, transposed: WS[m][k*64+c] = W[c*64+k]
    const float* srcs[11] = { rin_W1, rin_W1 + 4096, rin_W1 + 8192,
                              rin_W2, rin_W2 + 4096, rin_W2 + 8192,
                              rout_W1, rout_W1 + 4096,
                              rout_W2, rout_W2 + 4096,
                              W_v };
    for (int m = 0; m < 11; m++) {
        const float* src = srcs[m];
        float* dstw = WS + m * 4096;
        for (int idx = t; idx < 4096; idx += 256)
            dstw[(idx & 63) * 64 + (idx >> 6)] = src[idx];
    }
    if (t < 192) { SB[t] = rin_b1[t]; SB[192 + t] = rin_b2[t]; }
    if (t < 128) { SB[384 + t] = rout_b1[t]; SB[512 + t] = rout_b2[t]; SB[768 + t] = W_out[t]; }
    if (t < 64)  { SB[640 + t] = b_v[t]; SB[704 + t] = gate[t]; }
    if (t < 2)   { SB[896 + t] = b_out[t]; }
    __syncthreads();

    for (int tile = blockIdx.x; tile * 64 < N; tile += gridDim.x) {
        int base = tile * 64;
        __syncthreads();
        #pragma unroll
        for (int i = 0; i < 4; i++) {
            int row = base + ty * 4 + i;
            float4 v = make_float4(0.f, 0.f, 0.f, 0.f);
            if (row < N) v = *(const float4*)(g_v + (size_t)row * 64 + tx * 4);
            *(float4*)(V + (ty * 4 + i) * PITCH + tx * 4) = v;
        }

        // 3 "rin" residuals
        for (int r = 0; r < 3; r++)
            residual64(V, S, WS + r * 4096, SB + r * 64,
                       WS + (3 + r) * 4096, SB + 192 + r * 64, tx, ty);

        // v = sp(v) -> S (as matmul input for W_v)
        __syncthreads();
        #pragma unroll
        for (int i = 0; i < 4; i++) {
            float4 v = *(float4*)(V + (ty * 4 + i) * PITCH + tx * 4);
            v.x = sp_f(v.x); v.y = sp_f(v.y); v.z = sp_f(v.z); v.w = sp_f(v.w);
            *(float4*)(S + (ty * 4 + i) * PITCH + tx * 4) = v;
        }
        __syncthreads();
        float acc[4][4] = {};
        mm64(S, WS + 10 * 4096, tx, ty, acc);

        // updated_embedding = gate*pe + sp(v)@Wv^T + b_v  (write out + keep as x)
        #pragma unroll
        for (int i = 0; i < 4; i++) {
            int row = base + ty * 4 + i;
            float4 pe4 = make_float4(0.f, 0.f, 0.f, 0.f);
            if (row < N) pe4 = *(const float4*)(g_pe + (size_t)row * 64 + tx * 4);
            float4 u;
            u.x = fmaf(SB[704 + tx * 4 + 0], pe4.x, acc[i][0] + SB[640 + tx * 4 + 0]);
            u.y = fmaf(SB[704 + tx * 4 + 1], pe4.y, acc[i][1] + SB[640 + tx * 4 + 1]);
            u.z = fmaf(SB[704 + tx * 4 + 2], pe4.z, acc[i][2] + SB[640 + tx * 4 + 2]);
            u.w = fmaf(SB[704 + tx * 4 + 3], pe4.w, acc[i][3] + SB[640 + tx * 4 + 3]);
            *(float4*)(V + (ty * 4 + i) * PITCH + tx * 4) = u;
            if (row < N) *(float4*)(upd + (size_t)row * 64 + tx * 4) = u;
        }

        // 2 "rout" residuals
        for (int r = 0; r < 2; r++)
            residual64(V, S, WS + (6 + r) * 4096, SB + 384 + r * 64,
                       WS + (8 + r) * 4096, SB + 512 + r * 64, tx, ty);

        __syncthreads();
        // prediction = x @ W_out^T + b_out   (A=2)
        if (t < 128) {
            int r = t >> 1, a = t & 1;
            int row = base + r;
            if (row < N) {
                const float* wo = SB + 768 + a * 64;
                const float* xr = V + r * PITCH;
                float accp = SB[896 + a];
                #pragma unroll 8
                for (int k = 0; k < 64; k++) accp = fmaf(xr[k], wo[k], accp);
                pred[(size_t)row * 2 + a] = accp;
            }
        }
    }
}

// ---------------------------------------------------------------------------
extern "C" void kernel_launch(void* const* d_in, const int* in_sizes, int n_in,
                              void* d_out, int out_size)
{
    const float* emb     = (const float*)d_in[0];
    const float* f_ij    = (const float*)d_in[1];
    const int*   pidx    = (const int*)  d_in[2];
    const float* W_g     = (const float*)d_in[3];
    const float* W_i     = (const float*)d_in[4];
    const float* b_i     = (const float*)d_in[5];
    const float* W_j     = (const float*)d_in[6];
    const float* b_j     = (const float*)d_in[7];
    const float* W_v     = (const float*)d_in[8];
    const float* b_v     = (const float*)d_in[9];
    const float* gate    = (const float*)d_in[10];
    const float* rin_W1  = (const float*)d_in[11];
    const float* rin_b1  = (const float*)d_in[12];
    const float* rin_W2  = (const float*)d_in[13];
    const float* rin_b2  = (const float*)d_in[14];
    const float* rout_W1 = (const float*)d_in[15];
    const float* rout_b1 = (const float*)d_in[16];
    const float* rout_W2 = (const float*)d_in[17];
    const float* rout_b2 = (const float*)d_in[18];
    const float* W_out   = (const float*)d_in[19];
    const float* b_out   = (const float*)d_in[20];

    int N = in_sizes[0] / 64;
    int P = in_sizes[1] / 16;

    float* pred = (float*)d_out;                 // [N, 2]
    float* upd  = pred + (size_t)N * 2;          // [N, 64]

    int tiles = (N + 63) / 64;
    k1_atom<<<tiles, 256>>>(emb, W_i, b_i, W_j, b_j, N);
    k2_pair<<<2048, 256>>>(f_ij, pidx, W_g, P);

    int smem = (11 * 4096 + 2 * 64 * PITCH + 900) * (int)sizeof(float);
    cudaFuncSetAttribute(k3_out, cudaFuncAttributeMaxDynamicSharedMemorySize, smem);
    k3_out<<<152, 256, smem>>>(rin_W1, rin_b1, rin_W2, rin_b2,
                               rout_W1, rout_b1, rout_W2, rout_b2,
                               W_v, b_v, gate, W_out, b_out, pred, upd, N);
}

// round 3
// speedup vs baseline: 1.4848x; 1.4848x over previous
#include <cuda_runtime.h>
#include <math.h>

#define NMAX 100000
#define FDIM 64
#define PITCH 68   // 272B rows, 16B-aligned

__device__ float g_pe[(size_t)NMAX * FDIM];
__device__ float g_mj[(size_t)NMAX * FDIM];
__device__ float g_v [(size_t)NMAX * FDIM];

__device__ __forceinline__ float sp_f(float x) {
    return fmaxf(x, 0.0f) + log1pf(__expf(-fabsf(x)));
}

// 64x64x64 tile matmul: x [64 rows, PITCH] (shared), w transposed [k*64+c] (shared)
// thread (tx,ty) computes rows ty*4..+3, cols tx*4..+3
__device__ __forceinline__ void mm64(const float* __restrict__ x,
                                     const float* __restrict__ w,
                                     int tx, int ty, float acc[4][4])
{
    #pragma unroll 4
    for (int k0 = 0; k0 < 64; k0 += 4) {
        float4 a4[4];
        #pragma unroll
        for (int i = 0; i < 4; i++)
            a4[i] = *(const float4*)(x + (ty * 4 + i) * PITCH + k0);
        #pragma unroll
        for (int kk = 0; kk < 4; kk++) {
            float4 b4 = *(const float4*)(w + (k0 + kk) * 64 + tx * 4);
            #pragma unroll
            for (int i = 0; i < 4; i++) {
                float a = ((const float*)&a4[i])[kk];
                acc[i][0] = fmaf(a, b4.x, acc[i][0]);
                acc[i][1] = fmaf(a, b4.y, acc[i][1]);
                acc[i][2] = fmaf(a, b4.z, acc[i][2]);
                acc[i][3] = fmaf(a, b4.w, acc[i][3]);
            }
        }
    }
}

// ---------------------------------------------------------------------------
// K1: pe = sp(emb); v0 = sp(pe@Wi^T+bi); mj = sp(pe@Wj^T+bj)
// ---------------------------------------------------------------------------
__global__ void __launch_bounds__(256) k1_atom(
    const float* __restrict__ emb,
    const float* __restrict__ W_i, const float* __restrict__ b_i,
    const float* __restrict__ W_j, const float* __restrict__ b_j,
    int N)
{
    __shared__ float xs[64 * PITCH];
    __shared__ float ws[64 * 64];
    __shared__ float bs[64];
    int t  = threadIdx.x;
    int tx = t & 15, ty = t >> 4;
    int base = blockIdx.x * 64;

    #pragma unroll
    for (int i = 0; i < 4; i++) {
        int r = ty * 4 + i;
        int row = base + r;
        float4 v = make_float4(0.f, 0.f, 0.f, 0.f);
        if (row < N) v = *(const float4*)(emb + (size_t)row * 64 + tx * 4);
        v.x = sp_f(v.x); v.y = sp_f(v.y); v.z = sp_f(v.z); v.w = sp_f(v.w);
        *(float4*)(xs + r * PITCH + tx * 4) = v;
        if (row < N) *(float4*)(g_pe + (size_t)row * 64 + tx * 4) = v;
    }

    for (int pass = 0; pass < 2; pass++) {
        const float* W = pass ? W_j : W_i;
        const float* B = pass ? b_j : b_i;
        float* dst = pass ? g_mj : g_v;
        __syncthreads();
        for (int idx = t; idx < 4096; idx += 256)
            ws[(idx & 63) * 64 + (idx >> 6)] = W[idx];
        if (t < 64) bs[t] = B[t];
        __syncthreads();

        float acc[4][4] = {};
        mm64(xs, ws, tx, ty, acc);
        float4 bb = *(const float4*)(bs + tx * 4);
        #pragma unroll
        for (int i = 0; i < 4; i++) {
            int row = base + ty * 4 + i;
            if (row < N) {
                float4 o;
                o.x = sp_f(acc[i][0] + bb.x);
                o.y = sp_f(acc[i][1] + bb.y);
                o.z = sp_f(acc[i][2] + bb.z);
                o.w = sp_f(acc[i][3] + bb.w);
                *(float4*)(dst + (size_t)row * 64 + tx * 4) = o;
            }
        }
    }
}

// ---------------------------------------------------------------------------
// K2: pair scatter. 2 pairs per warp, 4 cols per lane, red.global.add.v4.f32
// ---------------------------------------------------------------------------
__global__ void __launch_bounds__(256) k2_pair(
    const float* __restrict__ f_ij,
    const int*   __restrict__ pidx,
    const float* __restrict__ W_g,
    int P)
{
    __shared__ float wgT[16 * 64];   // wgT[k*64+c] = W_g[c*16+k]
    __shared__ float fs[16][16];
    __shared__ int   si[16], sj[16];
    int t = threadIdx.x;
    for (int idx = t; idx < 1024; idx += 256) {
        int c = idx >> 4, k = idx & 15;
        wgT[k * 64 + c] = W_g[c * 16 + k];
    }
    int w = t >> 5, lane = t & 31, sub = lane >> 4, li = lane & 15;
    int c0 = li * 4;

    for (int base = blockIdx.x * 16; base < P; base += gridDim.x * 16) {
        __syncthreads();
        {   // stage 16 pairs of f_ij (one float per thread)
            int p = base + (t >> 4);
            fs[t >> 4][t & 15] = (p < P) ? f_ij[(size_t)p * 16 + (t & 15)] : 0.f;
        }
        if (t < 16) {
            int p = base + t;
            if (p < P) { si[t] = pidx[p]; sj[t] = pidx[P + p]; }
        }
        __syncthreads();
        int pl = w * 2 + sub;
        int p = base + pl;
        if (p < P) {
            int ai = si[pl], aj = sj[pl];
            float4 m = *(const float4*)(g_mj + (size_t)aj * 64 + c0);
            float4 a = make_float4(0.f, 0.f, 0.f, 0.f);
            #pragma unroll
            for (int k = 0; k < 16; k++) {
                float fk = fs[pl][k];
                float4 w4 = *(const float4*)(wgT + k * 64 + c0);
                a.x = fmaf(fk, w4.x, a.x);
                a.y = fmaf(fk, w4.y, a.y);
                a.z = fmaf(fk, w4.z, a.z);
                a.w = fmaf(fk, w4.w, a.w);
            }
            float* d = g_v + (size_t)ai * 64 + c0;
            asm volatile("red.global.add.v4.f32 [%0], {%1, %2, %3, %4};"
                         :: "l"(d), "f"(m.x * a.x), "f"(m.y * a.y),
                            "f"(m.z * a.z), "f"(m.w * a.w)
                         : "memory");
        }
    }
}

// ---------------------------------------------------------------------------
// K3: residual chain + output. Weights resident in shared; V tile in
// registers; 512 threads = 2 independent 256-thread groups w/ named barriers.
// ---------------------------------------------------------------------------
#define GBAR(id) asm volatile("bar.sync %0, 256;" :: "r"(id) : "memory")

__device__ __forceinline__ void residual_reg(float V[4][4], float* S,
                                             const float* w1, const float* b1,
                                             const float* w2, const float* b2,
                                             int tx, int ty, int barid)
{
    GBAR(barid);  // prior readers of S done
    #pragma unroll
    for (int i = 0; i < 4; i++) {
        float4 s;
        s.x = sp_f(V[i][0]); s.y = sp_f(V[i][1]);
        s.z = sp_f(V[i][2]); s.w = sp_f(V[i][3]);
        *(float4*)(S + (ty * 4 + i) * PITCH + tx * 4) = s;
    }
    GBAR(barid);
    float acc[4][4] = {};
    mm64(S, w1, tx, ty, acc);
    GBAR(barid);  // all mm1 reads done before overwrite
    float4 bb1 = *(const float4*)(b1 + tx * 4);
    #pragma unroll
    for (int i = 0; i < 4; i++) {
        float4 h;
        h.x = sp_f(acc[i][0] + bb1.x);
        h.y = sp_f(acc[i][1] + bb1.y);
        h.z = sp_f(acc[i][2] + bb1.z);
        h.w = sp_f(acc[i][3] + bb1.w);
        *(float4*)(S + (ty * 4 + i) * PITCH + tx * 4) = h;
    }
    GBAR(barid);
    float acc2[4][4] = {};
    mm64(S, w2, tx, ty, acc2);
    float4 bb2 = *(const float4*)(b2 + tx * 4);
    #pragma unroll
    for (int i = 0; i < 4; i++) {
        V[i][0] += acc2[i][0] + bb2.x;
        V[i][1] += acc2[i][1] + bb2.y;
        V[i][2] += acc2[i][2] + bb2.z;
        V[i][3] += acc2[i][3] + bb2.w;
    }
}

__global__ void __launch_bounds__(512) k3_out(
    const float* __restrict__ rin_W1, const float* __restrict__ rin_b1,
    const float* __restrict__ rin_W2, const float* __restrict__ rin_b2,
    const float* __restrict__ rout_W1, const float* __restrict__ rout_b1,
    const float* __restrict__ rout_W2, const float* __restrict__ rout_b2,
    const float* __restrict__ W_v, const float* __restrict__ b_v,
    const float* __restrict__ gate,
    const float* __restrict__ W_out, const float* __restrict__ b_out,
    float* __restrict__ pred, float* __restrict__ upd, int N)
{
    extern __shared__ float sm[];
    float* WS = sm;                      // 11 * 4096
    float* S0 = WS + 11 * 4096;          // 2 * 64 * PITCH
    float* SB = S0 + 2 * 64 * PITCH;     // small params (960)
    int t = threadIdx.x;
    int g = t >> 8;                      // tile group 0/1
    int gt = t & 255;
    int tx = gt & 15, ty = gt >> 4;
    int barid = g + 1;
    float* S = S0 + g * 64 * PITCH;

    const float* srcs[11] = { rin_W1, rin_W1 + 4096, rin_W1 + 8192,
                              rin_W2, rin_W2 + 4096, rin_W2 + 8192,
                              rout_W1, rout_W1 + 4096,
                              rout_W2, rout_W2 + 4096,
                              W_v };
    for (int m = 0; m < 11; m++) {
        const float* src = srcs[m];
        float* dstw = WS + m * 4096;
        for (int idx = t; idx < 4096; idx += 512)
            dstw[(idx & 63) * 64 + (idx >> 6)] = src[idx];
    }
    if (t < 192) { SB[t] = rin_b1[t]; SB[192 + t] = rin_b2[t]; }
    if (t < 128) { SB[384 + t] = rout_b1[t]; SB[512 + t] = rout_b2[t]; SB[768 + t] = W_out[t]; }
    if (t < 64)  { SB[640 + t] = b_v[t]; SB[704 + t] = gate[t]; }
    if (t < 2)   { SB[896 + t] = b_out[t]; }
    __syncthreads();

    float4 wo0 = *(const float4*)(SB + 768 + tx * 4);
    float4 wo1 = *(const float4*)(SB + 768 + 64 + tx * 4);
    float  bo0 = SB[896], bo1 = SB[897];
    float4 gt4 = *(const float4*)(SB + 704 + tx * 4);
    float4 bv4 = *(const float4*)(SB + 640 + tx * 4);

    for (int tile = blockIdx.x * 2 + g; tile * 64 < N; tile += gridDim.x * 2) {
        int base = tile * 64;
        float V[4][4];
        #pragma unroll
        for (int i = 0; i < 4; i++) {
            int row = base + ty * 4 + i;
            float4 v = make_float4(0.f, 0.f, 0.f, 0.f);
            if (row < N) v = *(const float4*)(g_v + (size_t)row * 64 + tx * 4);
            V[i][0] = v.x; V[i][1] = v.y; V[i][2] = v.z; V[i][3] = v.w;
        }

        #pragma unroll 1
        for (int r = 0; r < 3; r++)
            residual_reg(V, S, WS + r * 4096, SB + r * 64,
                         WS + (3 + r) * 4096, SB + 192 + r * 64, tx, ty, barid);

        // S = sp(V); acc = S @ Wv^T
        GBAR(barid);
        #pragma unroll
        for (int i = 0; i < 4; i++) {
            float4 s;
            s.x = sp_f(V[i][0]); s.y = sp_f(V[i][1]);
            s.z = sp_f(V[i][2]); s.w = sp_f(V[i][3]);
            *(float4*)(S + (ty * 4 + i) * PITCH + tx * 4) = s;
        }
        GBAR(barid);
        float acc[4][4] = {};
        mm64(S, WS + 10 * 4096, tx, ty, acc);

        // u = gate*pe + acc + b_v  -> V, store upd
        #pragma unroll
        for (int i = 0; i < 4; i++) {
            int row = base + ty * 4 + i;
            float4 pe4 = make_float4(0.f, 0.f, 0.f, 0.f);
            if (row < N) pe4 = *(const float4*)(g_pe + (size_t)row * 64 + tx * 4);
            float4 u;
            u.x = fmaf(gt4.x, pe4.x, acc[i][0] + bv4.x);
            u.y = fmaf(gt4.y, pe4.y, acc[i][1] + bv4.y);
            u.z = fmaf(gt4.z, pe4.z, acc[i][2] + bv4.z);
            u.w = fmaf(gt4.w, pe4.w, acc[i][3] + bv4.w);
            V[i][0] = u.x; V[i][1] = u.y; V[i][2] = u.z; V[i][3] = u.w;
            if (row < N) *(float4*)(upd + (size_t)row * 64 + tx * 4) = u;
        }

        #pragma unroll 1
        for (int r = 0; r < 2; r++)
            residual_reg(V, S, WS + (6 + r) * 4096, SB + 384 + r * 64,
                         WS + (8 + r) * 4096, SB + 512 + r * 64, tx, ty, barid);

        // prediction = V @ W_out^T + b_out via half-warp shfl reduction
        #pragma unroll
        for (int i = 0; i < 4; i++) {
            float p0 = V[i][0] * wo0.x + V[i][1] * wo0.y + V[i][2] * wo0.z + V[i][3] * wo0.w;
            float p1 = V[i][0] * wo1.x + V[i][1] * wo1.y + V[i][2] * wo1.z + V[i][3] * wo1.w;
            #pragma unroll
            for (int off = 8; off >= 1; off >>= 1) {
                p0 += __shfl_xor_sync(0xffffffffu, p0, off);
                p1 += __shfl_xor_sync(0xffffffffu, p1, off);
            }
            int row = base + ty * 4 + i;
            if (tx == 0 && row < N) {
                pred[(size_t)row * 2 + 0] = p0 + bo0;
                pred[(size_t)row * 2 + 1] = p1 + bo1;
            }
        }
    }
}

// ---------------------------------------------------------------------------
extern "C" void kernel_launch(void* const* d_in, const int* in_sizes, int n_in,
                              void* d_out, int out_size)
{
    const float* emb     = (const float*)d_in[0];
    const float* f_ij    = (const float*)d_in[1];
    const int*   pidx    = (const int*)  d_in[2];
    const float* W_g     = (const float*)d_in[3];
    const float* W_i     = (const float*)d_in[4];
    const float* b_i     = (const float*)d_in[5];
    const float* W_j     = (const float*)d_in[6];
    const float* b_j     = (const float*)d_in[7];
    const float* W_v     = (const float*)d_in[8];
    const float* b_v     = (const float*)d_in[9];
    const float* gate    = (const float*)d_in[10];
    const float* rin_W1  = (const float*)d_in[11];
    const float* rin_b1  = (const float*)d_in[12];
    const float* rin_W2  = (const float*)d_in[13];
    const float* rin_b2  = (const float*)d_in[14];
    const float* rout_W1 = (const float*)d_in[15];
    const float* rout_b1 = (const float*)d_in[16];
    const float* rout_W2 = (const float*)d_in[17];
    const float* rout_b2 = (const float*)d_in[18];
    const float* W_out   = (const float*)d_in[19];
    const float* b_out   = (const float*)d_in[20];

    int N = in_sizes[0] / 64;
    int P = in_sizes[1] / 16;

    float* pred = (float*)d_out;                 // [N, 2]
    float* upd  = pred + (size_t)N * 2;          // [N, 64]

    int tiles = (N + 63) / 64;
    k1_atom<<<tiles, 256>>>(emb, W_i, b_i, W_j, b_j, N);
    k2_pair<<<4096, 256>>>(f_ij, pidx, W_g, P);

    int smem = (11 * 4096 + 2 * 64 * PITCH + 960) * (int)sizeof(float);
    cudaFuncSetAttribute(k3_out, cudaFuncAttributeMaxDynamicSharedMemorySize, smem);
    k3_out<<<152, 512, smem>>>(rin_W1, rin_b1, rin_W2, rin_b2,
                               rout_W1, rout_b1, rout_W2, rout_b2,
                               W_v, b_v, gate, W_out, b_out, pred, upd, N);
}

// round 4
// speedup vs baseline: 1.4921x; 1.0049x over previous
#include <cuda_runtime.h>
#include <math.h>

#define NMAX 100000
#define FDIM 64
#define PITCH 68   // 272B rows, 16B-aligned

__device__ float g_pe[(size_t)NMAX * FDIM];
__device__ float g_mj[(size_t)NMAX * FDIM];
__device__ float g_v [(size_t)NMAX * FDIM];

__device__ __forceinline__ float sp_f(float x) {
    return fmaxf(x, 0.0f) + log1pf(__expf(-fabsf(x)));
}

// ---- packed f32x2 helpers (Blackwell FFMA2) --------------------------------
__device__ __forceinline__ unsigned long long dupf2(float a) {
    unsigned long long r;
    asm("mov.b64 %0, {%1, %1};" : "=l"(r) : "r"(__float_as_uint(a)));
    return r;
}
__device__ __forceinline__ void ffma2(unsigned long long& acc,
                                      unsigned long long a, unsigned long long b) {
    asm("fma.rn.f32x2 %0, %1, %2, %0;" : "+l"(acc) : "l"(a), "l"(b));
}
__device__ __forceinline__ float2 unpk(unsigned long long v) {
    unsigned int lo, hi;
    asm("mov.b64 {%0, %1}, %2;" : "=r"(lo), "=r"(hi) : "l"(v));
    return make_float2(__uint_as_float(lo), __uint_as_float(hi));
}

// 64x64x64 tile matmul with packed FFMA2.
// x: [64 rows, PITCH] shared; w: transposed [k*64+c] shared.
// thread (tx,ty) -> rows ty*4..+3, cols tx*4..+3; acc01 = cols {0,1}, acc23 = {2,3}
__device__ __forceinline__ void mm64_f2(const float* __restrict__ x,
                                        const float* __restrict__ w,
                                        int tx, int ty,
                                        unsigned long long acc01[4],
                                        unsigned long long acc23[4])
{
    #pragma unroll 4
    for (int k0 = 0; k0 < 64; k0 += 4) {
        float4 a4[4];
        #pragma unroll
        for (int i = 0; i < 4; i++)
            a4[i] = *(const float4*)(x + (ty * 4 + i) * PITCH + k0);
        #pragma unroll
        for (int kk = 0; kk < 4; kk++) {
            ulonglong2 b2 = *(const ulonglong2*)(w + (k0 + kk) * 64 + tx * 4);
            #pragma unroll
            for (int i = 0; i < 4; i++) {
                unsigned long long aa = dupf2(((const float*)&a4[i])[kk]);
                ffma2(acc01[i], aa, b2.x);
                ffma2(acc23[i], aa, b2.y);
            }
        }
    }
}

// ---------------------------------------------------------------------------
// K1 (fused): pe = sp(emb); v0 = sp(pe@Wi^T+bi); mj = sp(pe@Wj^T+bj)
// Both weight matmuls in ONE k-loop sharing a-fragments and a-dups.
// ---------------------------------------------------------------------------
__global__ void __launch_bounds__(256) k1_atom(
    const float* __restrict__ emb,
    const float* __restrict__ W_i, const float* __restrict__ b_i,
    const float* __restrict__ W_j, const float* __restrict__ b_j,
    int N)
{
    extern __shared__ float dsm[];
    float* xs = dsm;                 // 64*PITCH
    float* wi = xs + 64 * PITCH;     // 4096
    float* wj = wi + 4096;           // 4096
    __shared__ float bsi[64], bsj[64];
    int t  = threadIdx.x;
    int tx = t & 15, ty = t >> 4;
    int base = blockIdx.x * 64;

    #pragma unroll
    for (int i = 0; i < 4; i++) {
        int r = ty * 4 + i;
        int row = base + r;
        float4 v = make_float4(0.f, 0.f, 0.f, 0.f);
        if (row < N) v = *(const float4*)(emb + (size_t)row * 64 + tx * 4);
        v.x = sp_f(v.x); v.y = sp_f(v.y); v.z = sp_f(v.z); v.w = sp_f(v.w);
        *(float4*)(xs + r * PITCH + tx * 4) = v;
        if (row < N) *(float4*)(g_pe + (size_t)row * 64 + tx * 4) = v;
    }
    for (int idx = t; idx < 4096; idx += 256) {
        int c = idx >> 6, k = idx & 63;
        wi[k * 64 + c] = W_i[idx];
        wj[k * 64 + c] = W_j[idx];
    }
    if (t < 64) { bsi[t] = b_i[t]; bsj[t] = b_j[t]; }
    __syncthreads();

    unsigned long long aI01[4] = {}, aI23[4] = {}, aJ01[4] = {}, aJ23[4] = {};
    #pragma unroll 2
    for (int k0 = 0; k0 < 64; k0 += 4) {
        float4 a4[4];
        #pragma unroll
        for (int i = 0; i < 4; i++)
            a4[i] = *(const float4*)(xs + (ty * 4 + i) * PITCH + k0);
        #pragma unroll
        for (int kk = 0; kk < 4; kk++) {
            ulonglong2 bi2 = *(const ulonglong2*)(wi + (k0 + kk) * 64 + tx * 4);
            ulonglong2 bj2 = *(const ulonglong2*)(wj + (k0 + kk) * 64 + tx * 4);
            #pragma unroll
            for (int i = 0; i < 4; i++) {
                unsigned long long aa = dupf2(((const float*)&a4[i])[kk]);
                ffma2(aI01[i], aa, bi2.x);
                ffma2(aI23[i], aa, bi2.y);
                ffma2(aJ01[i], aa, bj2.x);
                ffma2(aJ23[i], aa, bj2.y);
            }
        }
    }

    float4 bbi = *(const float4*)(bsi + tx * 4);
    float4 bbj = *(const float4*)(bsj + tx * 4);
    #pragma unroll
    for (int i = 0; i < 4; i++) {
        int row = base + ty * 4 + i;
        if (row < N) {
            float2 i01 = unpk(aI01[i]), i23 = unpk(aI23[i]);
            float2 j01 = unpk(aJ01[i]), j23 = unpk(aJ23[i]);
            float4 ov, om;
            ov.x = sp_f(i01.x + bbi.x); ov.y = sp_f(i01.y + bbi.y);
            ov.z = sp_f(i23.x + bbi.z); ov.w = sp_f(i23.y + bbi.w);
            om.x = sp_f(j01.x + bbj.x); om.y = sp_f(j01.y + bbj.y);
            om.z = sp_f(j23.x + bbj.z); om.w = sp_f(j23.y + bbj.w);
            *(float4*)(g_v  + (size_t)row * 64 + tx * 4) = ov;
            *(float4*)(g_mj + (size_t)row * 64 + tx * 4) = om;
        }
    }
}

// ---------------------------------------------------------------------------
// K2: pair scatter. 2 pairs/warp, 4 cols/lane, red.global.add.v4.f32
// ---------------------------------------------------------------------------
__global__ void __launch_bounds__(256) k2_pair(
    const float* __restrict__ f_ij,
    const int*   __restrict__ pidx,
    const float* __restrict__ W_g,
    int P)
{
    __shared__ float wgT[16 * 64];   // wgT[k*64+c] = W_g[c*16+k]
    __shared__ float fs[16][16];
    __shared__ int   si[16], sj[16];
    int t = threadIdx.x;
    for (int idx = t; idx < 1024; idx += 256) {
        int c = idx >> 4, k = idx & 15;
        wgT[k * 64 + c] = W_g[c * 16 + k];
    }
    int w = t >> 5, lane = t & 31, sub = lane >> 4, li = lane & 15;
    int c0 = li * 4;

    for (int base = blockIdx.x * 16; base < P; base += gridDim.x * 16) {
        __syncthreads();
        {
            int p = base + (t >> 4);
            fs[t >> 4][t & 15] = (p < P) ? __ldcs(f_ij + (size_t)p * 16 + (t & 15)) : 0.f;
        }
        if (t < 16) {
            int p = base + t;
            if (p < P) { si[t] = __ldcs(pidx + p); sj[t] = __ldcs(pidx + P + p); }
        }
        __syncthreads();
        int pl = w * 2 + sub;
        int p = base + pl;
        if (p < P) {
            int ai = si[pl], aj = sj[pl];
            float4 m = *(const float4*)(g_mj + (size_t)aj * 64 + c0);
            float4 a = make_float4(0.f, 0.f, 0.f, 0.f);
            #pragma unroll
            for (int k = 0; k < 16; k++) {
                float fk = fs[pl][k];
                float4 w4 = *(const float4*)(wgT + k * 64 + c0);
                a.x = fmaf(fk, w4.x, a.x);
                a.y = fmaf(fk, w4.y, a.y);
                a.z = fmaf(fk, w4.z, a.z);
                a.w = fmaf(fk, w4.w, a.w);
            }
            float* d = g_v + (size_t)ai * 64 + c0;
            asm volatile("red.global.add.v4.f32 [%0], {%1, %2, %3, %4};"
                         :: "l"(d), "f"(m.x * a.x), "f"(m.y * a.y),
                            "f"(m.z * a.z), "f"(m.w * a.w)
                         : "memory");
        }
    }
}

// ---------------------------------------------------------------------------
// K3: residual chain + output; FFMA2 matmuls; 2 groups of 256 thr.
// ---------------------------------------------------------------------------
#define GBAR(id) asm volatile("bar.sync %0, 256;" :: "r"(id) : "memory")

__device__ __forceinline__ void residual_reg(float V[4][4], float* S,
                                             const float* w1, const float* b1,
                                             const float* w2, const float* b2,
                                             int tx, int ty, int barid)
{
    GBAR(barid);
    #pragma unroll
    for (int i = 0; i < 4; i++) {
        float4 s;
        s.x = sp_f(V[i][0]); s.y = sp_f(V[i][1]);
        s.z = sp_f(V[i][2]); s.w = sp_f(V[i][3]);
        *(float4*)(S + (ty * 4 + i) * PITCH + tx * 4) = s;
    }
    GBAR(barid);
    unsigned long long a01[4] = {}, a23[4] = {};
    mm64_f2(S, w1, tx, ty, a01, a23);
    GBAR(barid);
    float4 bb1 = *(const float4*)(b1 + tx * 4);
    #pragma unroll
    for (int i = 0; i < 4; i++) {
        float2 p01 = unpk(a01[i]), p23 = unpk(a23[i]);
        float4 h;
        h.x = sp_f(p01.x + bb1.x);
        h.y = sp_f(p01.y + bb1.y);
        h.z = sp_f(p23.x + bb1.z);
        h.w = sp_f(p23.y + bb1.w);
        *(float4*)(S + (ty * 4 + i) * PITCH + tx * 4) = h;
    }
    GBAR(barid);
    unsigned long long c01[4] = {}, c23[4] = {};
    mm64_f2(S, w2, tx, ty, c01, c23);
    float4 bb2 = *(const float4*)(b2 + tx * 4);
    #pragma unroll
    for (int i = 0; i < 4; i++) {
        float2 p01 = unpk(c01[i]), p23 = unpk(c23[i]);
        V[i][0] += p01.x + bb2.x;
        V[i][1] += p01.y + bb2.y;
        V[i][2] += p23.x + bb2.z;
        V[i][3] += p23.y + bb2.w;
    }
}

__global__ void __launch_bounds__(512) k3_out(
    const float* __restrict__ rin_W1, const float* __restrict__ rin_b1,
    const float* __restrict__ rin_W2, const float* __restrict__ rin_b2,
    const float* __restrict__ rout_W1, const float* __restrict__ rout_b1,
    const float* __restrict__ rout_W2, const float* __restrict__ rout_b2,
    const float* __restrict__ W_v, const float* __restrict__ b_v,
    const float* __restrict__ gate,
    const float* __restrict__ W_out, const float* __restrict__ b_out,
    float* __restrict__ pred, float* __restrict__ upd, int N)
{
    extern __shared__ float sm[];
    float* WS = sm;                      // 11 * 4096
    float* S0 = WS + 11 * 4096;          // 2 * 64 * PITCH
    float* SB = S0 + 2 * 64 * PITCH;     // small params
    int t = threadIdx.x;
    int g = t >> 8;
    int gt = t & 255;
    int tx = gt & 15, ty = gt >> 4;
    int barid = g + 1;
    float* S = S0 + g * 64 * PITCH;

    const float* srcs[11] = { rin_W1, rin_W1 + 4096, rin_W1 + 8192,
                              rin_W2, rin_W2 + 4096, rin_W2 + 8192,
                              rout_W1, rout_W1 + 4096,
                              rout_W2, rout_W2 + 4096,
                              W_v };
    for (int m = 0; m < 11; m++) {
        const float* src = srcs[m];
        float* dstw = WS + m * 4096;
        for (int idx = t; idx < 4096; idx += 512)
            dstw[(idx & 63) * 64 + (idx >> 6)] = src[idx];
    }
    if (t < 192) { SB[t] = rin_b1[t]; SB[192 + t] = rin_b2[t]; }
    if (t < 128) { SB[384 + t] = rout_b1[t]; SB[512 + t] = rout_b2[t]; SB[768 + t] = W_out[t]; }
    if (t < 64)  { SB[640 + t] = b_v[t]; SB[704 + t] = gate[t]; }
    if (t < 2)   { SB[896 + t] = b_out[t]; }
    __syncthreads();

    float4 wo0 = *(const float4*)(SB + 768 + tx * 4);
    float4 wo1 = *(const float4*)(SB + 768 + 64 + tx * 4);
    float  bo0 = SB[896], bo1 = SB[897];
    float4 gt4 = *(const float4*)(SB + 704 + tx * 4);
    float4 bv4 = *(const float4*)(SB + 640 + tx * 4);

    for (int tile = blockIdx.x * 2 + g; tile * 64 < N; tile += gridDim.x * 2) {
        int base = tile * 64;
        float V[4][4];
        #pragma unroll
        for (int i = 0; i < 4; i++) {
            int row = base + ty * 4 + i;
            float4 v = make_float4(0.f, 0.f, 0.f, 0.f);
            if (row < N) v = *(const float4*)(g_v + (size_t)row * 64 + tx * 4);
            V[i][0] = v.x; V[i][1] = v.y; V[i][2] = v.z; V[i][3] = v.w;
        }

        #pragma unroll 1
        for (int r = 0; r < 3; r++)
            residual_reg(V, S, WS + r * 4096, SB + r * 64,
                         WS + (3 + r) * 4096, SB + 192 + r * 64, tx, ty, barid);

        GBAR(barid);
        #pragma unroll
        for (int i = 0; i < 4; i++) {
            float4 s;
            s.x = sp_f(V[i][0]); s.y = sp_f(V[i][1]);
            s.z = sp_f(V[i][2]); s.w = sp_f(V[i][3]);
            *(float4*)(S + (ty * 4 + i) * PITCH + tx * 4) = s;
        }
        GBAR(barid);
        unsigned long long a01[4] = {}, a23[4] = {};
        mm64_f2(S, WS + 10 * 4096, tx, ty, a01, a23);

        #pragma unroll
        for (int i = 0; i < 4; i++) {
            int row = base + ty * 4 + i;
            float4 pe4 = make_float4(0.f, 0.f, 0.f, 0.f);
            if (row < N) pe4 = *(const float4*)(g_pe + (size_t)row * 64 + tx * 4);
            float2 p01 = unpk(a01[i]), p23 = unpk(a23[i]);
            float4 u;
            u.x = fmaf(gt4.x, pe4.x, p01.x + bv4.x);
            u.y = fmaf(gt4.y, pe4.y, p01.y + bv4.y);
            u.z = fmaf(gt4.z, pe4.z, p23.x + bv4.z);
            u.w = fmaf(gt4.w, pe4.w, p23.y + bv4.w);
            V[i][0] = u.x; V[i][1] = u.y; V[i][2] = u.z; V[i][3] = u.w;
            if (row < N) *(float4*)(upd + (size_t)row * 64 + tx * 4) = u;
        }

        #pragma unroll 1
        for (int r = 0; r < 2; r++)
            residual_reg(V, S, WS + (6 + r) * 4096, SB + 384 + r * 64,
                         WS + (8 + r) * 4096, SB + 512 + r * 64, tx, ty, barid);

        #pragma unroll
        for (int i = 0; i < 4; i++) {
            float p0 = V[i][0] * wo0.x + V[i][1] * wo0.y + V[i][2] * wo0.z + V[i][3] * wo0.w;
            float p1 = V[i][0] * wo1.x + V[i][1] * wo1.y + V[i][2] * wo1.z + V[i][3] * wo1.w;
            #pragma unroll
            for (int off = 8; off >= 1; off >>= 1) {
                p0 += __shfl_xor_sync(0xffffffffu, p0, off);
                p1 += __shfl_xor_sync(0xffffffffu, p1, off);
            }
            int row = base + ty * 4 + i;
            if (tx == 0 && row < N) {
                pred[(size_t)row * 2 + 0] = p0 + bo0;
                pred[(size_t)row * 2 + 1] = p1 + bo1;
            }
        }
    }
}

// ---------------------------------------------------------------------------
extern "C" void kernel_launch(void* const* d_in, const int* in_sizes, int n_in,
                              void* d_out, int out_size)
{
    const float* emb     = (const float*)d_in[0];
    const float* f_ij    = (const float*)d_in[1];
    const int*   pidx    = (const int*)  d_in[2];
    const float* W_g     = (const float*)d_in[3];
    const float* W_i     = (const float*)d_in[4];
    const float* b_i     = (const float*)d_in[5];
    const float* W_j     = (const float*)d_in[6];
    const float* b_j     = (const float*)d_in[7];
    const float* W_v     = (const float*)d_in[8];
    const float* b_v     = (const float*)d_in[9];
    const float* gate    = (const float*)d_in[10];
    const float* rin_W1  = (const float*)d_in[11];
    const float* rin_b1  = (const float*)d_in[12];
    const float* rin_W2  = (const float*)d_in[13];
    const float* rin_b2  = (const float*)d_in[14];
    const float* rout_W1 = (const float*)d_in[15];
    const float* rout_b1 = (const float*)d_in[16];
    const float* rout_W2 = (const float*)d_in[17];
    const float* rout_b2 = (const float*)d_in[18];
    const float* W_out   = (const float*)d_in[19];
    const float* b_out   = (const float*)d_in[20];

    int N = in_sizes[0] / 64;
    int P = in_sizes[1] / 16;

    float* pred = (float*)d_out;                 // [N, 2]
    float* upd  = pred + (size_t)N * 2;          // [N, 64]

    int tiles = (N + 63) / 64;
    int smem1 = (64 * PITCH + 2 * 4096) * (int)sizeof(float);
    cudaFuncSetAttribute(k1_atom, cudaFuncAttributeMaxDynamicSharedMemorySize, smem1);
    k1_atom<<<tiles, 256, smem1>>>(emb, W_i, b_i, W_j, b_j, N);
    k2_pair<<<4096, 256>>>(f_ij, pidx, W_g, P);

    int smem = (11 * 4096 + 2 * 64 * PITCH + 960) * (int)sizeof(float);
    cudaFuncSetAttribute(k3_out, cudaFuncAttributeMaxDynamicSharedMemorySize, smem);
    k3_out<<<152, 512, smem>>>(rin_W1, rin_b1, rin_W2, rin_b2,
                               rout_W1, rout_b1, rout_W2, rout_b2,
                               W_v, b_v, gate, W_out, b_out, pred, upd, N);
}